// round 2
// baseline (speedup 1.0000x reference)
#include <cuda_runtime.h>

#define BB 4
#define SS 4096
#define DM 1024
#define DK 64

// Scratch (device globals per allocation-guard rules): 4 MB each
__device__ float g_qh[BB * SS * DK];
__device__ float g_kh[BB * SS * DK];
__device__ float g_vh[BB * SS * DK];
__device__ float g_att[BB * SS * DK];

// ---------------------------------------------------------------------------
// Projection: out[m, n] = sum_d X[m, d] * W[n, d] + bias[n]
// M = B*S = 16384, N = 64, K = 1024.  Block: 64 rows x 64 cols, 256 threads,
// 4x4 register tile per thread, K-chunks of 32.
// which: 0 -> g_qh, 1 -> g_kh, 2 -> g_vh
// ---------------------------------------------------------------------------
__global__ __launch_bounds__(256) void proj_kernel(const float* __restrict__ X,
                                                   const float* __restrict__ W,
                                                   const float* __restrict__ bias,
                                                   int which)
{
    __shared__ float Xs[64][32];   // broadcast reads -> no pad needed
    __shared__ float Ws[64][33];   // padded -> conflict-free strided reads

    float* out = (which == 0) ? g_qh : (which == 1) ? g_kh : g_vh;

    const int m0 = blockIdx.x * 64;
    const int t  = threadIdx.x;
    const int ty = t >> 4;         // 0..15 (row group)
    const int tx = t & 15;         // 0..15 (col group)

    float acc[4][4] = {};

    for (int k0 = 0; k0 < DM; k0 += 32) {
        // X tile: 64x32 = 512 float4, 2 per thread
        #pragma unroll
        for (int j = 0; j < 2; j++) {
            int f   = t + j * 256;
            int row = f >> 3;
            int c4  = (f & 7) << 2;
            *(float4*)&Xs[row][c4] =
                *(const float4*)&X[(size_t)(m0 + row) * DM + k0 + c4];
        }
        // W tile: 64x32 scalar loads (coalesced)
        #pragma unroll
        for (int j = 0; j < 8; j++) {
            int f  = t + j * 256;
            int n  = f >> 5;
            int kk = f & 31;
            Ws[n][kk] = W[(size_t)n * DM + k0 + kk];
        }
        __syncthreads();

        #pragma unroll
        for (int kk = 0; kk < 32; kk++) {
            float a[4], bv[4];
            #pragma unroll
            for (int r = 0; r < 4; r++) a[r] = Xs[ty * 4 + r][kk];
            #pragma unroll
            for (int c = 0; c < 4; c++) bv[c] = Ws[tx * 4 + c][kk];
            #pragma unroll
            for (int r = 0; r < 4; r++)
                #pragma unroll
                for (int c = 0; c < 4; c++)
                    acc[r][c] += a[r] * bv[c];
        }
        __syncthreads();
    }

    #pragma unroll
    for (int r = 0; r < 4; r++) {
        int m = m0 + ty * 4 + r;
        #pragma unroll
        for (int c = 0; c < 4; c++) {
            int n = tx * 4 + c;
            out[(size_t)m * DK + n] = acc[r][c] + bias[n];
        }
    }
}

// ---------------------------------------------------------------------------
// Flash-attention: one block = 64 queries of one batch. Online softmax over
// key tiles of 32. mask[0, q, m] == 0 -> score = -1e9 (matches reference).
// ---------------------------------------------------------------------------
__global__ __launch_bounds__(256) void attn_kernel(const int* __restrict__ mask)
{
    __shared__ float Qs[64][64];   // broadcast reads
    __shared__ float Ks[32][65];   // padded
    __shared__ float Vs[32][65];   // padded
    __shared__ float Ps[64][33];   // padded

    const int b  = blockIdx.y;
    const int q0 = blockIdx.x * 64;
    const int t  = threadIdx.x;
    const int ty = t >> 4;
    const int tx = t & 15;
    const float scale = 0.125f;    // 1/sqrt(64)

    const float* qh = g_qh + ((size_t)b * SS + q0) * DK;

    // Load Q tile (64x64): 1024 float4, 4 per thread
    #pragma unroll
    for (int j = 0; j < 4; j++) {
        int f   = t + j * 256;
        int row = f >> 4;
        int c4  = (f & 15) << 2;
        *(float4*)&Qs[row][c4] = *(const float4*)&qh[row * DK + c4];
    }

    float m_i[4], l_i[4], acc[4][4] = {};
    #pragma unroll
    for (int r = 0; r < 4; r++) { m_i[r] = -1e30f; l_i[r] = 0.0f; }

    __syncthreads();

    for (int k0 = 0; k0 < SS; k0 += 32) {
        const float* kh = g_kh + ((size_t)b * SS + k0) * DK;
        const float* vh = g_vh + ((size_t)b * SS + k0) * DK;

        // Load K,V tiles (32x64 each): 512 float4 each, 2 per thread
        #pragma unroll
        for (int j = 0; j < 2; j++) {
            int f   = t + j * 256;
            int row = f >> 4;
            int c4  = (f & 15) << 2;
            float4 kv = *(const float4*)&kh[row * DK + c4];
            Ks[row][c4 + 0] = kv.x; Ks[row][c4 + 1] = kv.y;
            Ks[row][c4 + 2] = kv.z; Ks[row][c4 + 3] = kv.w;
            float4 vv = *(const float4*)&vh[row * DK + c4];
            Vs[row][c4 + 0] = vv.x; Vs[row][c4 + 1] = vv.y;
            Vs[row][c4 + 2] = vv.z; Vs[row][c4 + 3] = vv.w;
        }
        __syncthreads();

        // GEMM1: s[r][c] = Q[row] . K[key],  rows = ty*4+r, keys = tx*2+c
        float s[4][2] = {};
        #pragma unroll
        for (int kk = 0; kk < 64; kk++) {
            float a[4], bv2[2];
            #pragma unroll
            for (int r = 0; r < 4; r++) a[r] = Qs[ty * 4 + r][kk];
            #pragma unroll
            for (int c = 0; c < 2; c++) bv2[c] = Ks[tx * 2 + c][kk];
            #pragma unroll
            for (int r = 0; r < 4; r++)
                #pragma unroll
                for (int c = 0; c < 2; c++)
                    s[r][c] += a[r] * bv2[c];
        }

        // scale + mask (reference: where(mask==0, -1e9, scores*scale-after-scale))
        #pragma unroll
        for (int r = 0; r < 4; r++) {
            int q = q0 + ty * 4 + r;
            #pragma unroll
            for (int c = 0; c < 2; c++) {
                int key = k0 + tx * 2 + c;
                int mv  = mask[(size_t)q * SS + key];
                s[r][c] = mv ? s[r][c] * scale : -1e9f;
            }
        }

        // row max over the 32 keys (2 local + shuffle over 16 lanes)
        float mnew[4];
        #pragma unroll
        for (int r = 0; r < 4; r++) mnew[r] = fmaxf(s[r][0], s[r][1]);
        #pragma unroll
        for (int off = 8; off > 0; off >>= 1) {
            #pragma unroll
            for (int r = 0; r < 4; r++)
                mnew[r] = fmaxf(mnew[r], __shfl_xor_sync(0xffffffffu, mnew[r], off, 16));
        }

        float corr[4];
        #pragma unroll
        for (int r = 0; r < 4; r++) {
            float mn = fmaxf(m_i[r], mnew[r]);
            corr[r]  = __expf(m_i[r] - mn);
            m_i[r]   = mn;
        }

        float p[4][2], psum[4];
        #pragma unroll
        for (int r = 0; r < 4; r++) {
            p[r][0] = __expf(s[r][0] - m_i[r]);
            p[r][1] = __expf(s[r][1] - m_i[r]);
            psum[r] = p[r][0] + p[r][1];
        }
        #pragma unroll
        for (int off = 8; off > 0; off >>= 1) {
            #pragma unroll
            for (int r = 0; r < 4; r++)
                psum[r] += __shfl_xor_sync(0xffffffffu, psum[r], off, 16);
        }
        #pragma unroll
        for (int r = 0; r < 4; r++)
            l_i[r] = l_i[r] * corr[r] + psum[r];

        // stage P, rescale accumulators
        #pragma unroll
        for (int r = 0; r < 4; r++) {
            Ps[ty * 4 + r][tx * 2 + 0] = p[r][0];
            Ps[ty * 4 + r][tx * 2 + 1] = p[r][1];
            #pragma unroll
            for (int c = 0; c < 4; c++) acc[r][c] *= corr[r];
        }
        __syncthreads();

        // GEMM2: acc += P @ V  (keys = kk, dv cols = tx*4+c)
        #pragma unroll
        for (int kk = 0; kk < 32; kk++) {
            float a[4], bv[4];
            #pragma unroll
            for (int r = 0; r < 4; r++) a[r] = Ps[ty * 4 + r][kk];
            #pragma unroll
            for (int c = 0; c < 4; c++) bv[c] = Vs[kk][tx * 4 + c];
            #pragma unroll
            for (int r = 0; r < 4; r++)
                #pragma unroll
                for (int c = 0; c < 4; c++)
                    acc[r][c] += a[r] * bv[c];
        }
        __syncthreads();
    }

    float* out = g_att + ((size_t)b * SS + q0) * DK;
    #pragma unroll
    for (int r = 0; r < 4; r++) {
        float inv = 1.0f / l_i[r];
        #pragma unroll
        for (int c = 0; c < 4; c++)
            out[(ty * 4 + r) * DK + tx * 4 + c] = acc[r][c] * inv;
    }
}

// ---------------------------------------------------------------------------
// Output projection: out[m, n] = sum_v att[m, v] * Wo[n, v] + bo[n]
// M = 16384, N = 1024, K = 64. Block: 64x64 tile.
// ---------------------------------------------------------------------------
__global__ __launch_bounds__(256) void outproj_kernel(const float* __restrict__ Wo,
                                                      const float* __restrict__ bo,
                                                      float* __restrict__ out)
{
    __shared__ float As[64][64];   // broadcast reads
    __shared__ float Ws[64][65];   // padded

    const int m0 = blockIdx.x * 64;
    const int n0 = blockIdx.y * 64;
    const int t  = threadIdx.x;
    const int ty = t >> 4;
    const int tx = t & 15;

    // att tile: 64x64 = 1024 float4, 4 per thread
    #pragma unroll
    for (int j = 0; j < 4; j++) {
        int f   = t + j * 256;
        int row = f >> 4;
        int c4  = (f & 15) << 2;
        *(float4*)&As[row][c4] =
            *(const float4*)&g_att[(size_t)(m0 + row) * DK + c4];
    }
    // Wo tile: 64 rows (n) x 64 cols (v), scalar coalesced
    #pragma unroll
    for (int j = 0; j < 16; j++) {
        int f = t + j * 256;
        int n = f >> 6;
        int v = f & 63;
        Ws[n][v] = Wo[(size_t)(n0 + n) * DK + v];
    }
    __syncthreads();

    float acc[4][4] = {};
    #pragma unroll
    for (int kk = 0; kk < 64; kk++) {
        float a[4], bv[4];
        #pragma unroll
        for (int r = 0; r < 4; r++) a[r] = As[ty * 4 + r][kk];
        #pragma unroll
        for (int c = 0; c < 4; c++) bv[c] = Ws[tx * 4 + c][kk];
        #pragma unroll
        for (int r = 0; r < 4; r++)
            #pragma unroll
            for (int c = 0; c < 4; c++)
                acc[r][c] += a[r] * bv[c];
    }

    #pragma unroll
    for (int r = 0; r < 4; r++) {
        int m = m0 + ty * 4 + r;
        int n = n0 + tx * 4;
        float4 o;
        o.x = acc[r][0] + bo[n + 0];
        o.y = acc[r][1] + bo[n + 1];
        o.z = acc[r][2] + bo[n + 2];
        o.w = acc[r][3] + bo[n + 3];
        *(float4*)&out[(size_t)m * DM + n] = o;
    }
}

// ---------------------------------------------------------------------------
extern "C" void kernel_launch(void* const* d_in, const int* in_sizes, int n_in,
                              void* d_out, int out_size)
{
    const float* q    = (const float*)d_in[0];
    const float* k    = (const float*)d_in[1];
    const float* v    = (const float*)d_in[2];
    const int*   mask = (const int*)  d_in[3];
    const float* Wq   = (const float*)d_in[4];
    const float* bq   = (const float*)d_in[5];
    const float* Wk   = (const float*)d_in[6];
    const float* bk   = (const float*)d_in[7];
    const float* Wv   = (const float*)d_in[8];
    const float* bv   = (const float*)d_in[9];
    const float* Wo   = (const float*)d_in[10];
    const float* bo   = (const float*)d_in[11];
    float* out = (float*)d_out;

    const int M = BB * SS;  // 16384

    proj_kernel<<<M / 64, 256>>>(q, Wq, bq, 0);
    proj_kernel<<<M / 64, 256>>>(k, Wk, bk, 1);
    proj_kernel<<<M / 64, 256>>>(v, Wv, bv, 2);

    attn_kernel<<<dim3(SS / 64, BB), 256>>>(mask);

    outproj_kernel<<<dim3(M / 64, DM / 64), 256>>>(Wo, bo, out);
}

// round 3
// speedup vs baseline: 1.5055x; 1.5055x over previous
#include <cuda_runtime.h>
#include <cstdint>

#define BB 4
#define SS 4096
#define DM 1024
#define DK 64

// Scratch (device globals per allocation-guard rules): 4 MB each
__device__ float g_qh[BB * SS * DK];
__device__ float g_kh[BB * SS * DK];
__device__ float g_vh[BB * SS * DK];
__device__ float g_att[BB * SS * DK];

// ---------------------------------------------------------------------------
// tf32 helpers
// ---------------------------------------------------------------------------
__device__ __forceinline__ uint32_t f2tf(float f) {
    uint32_t u;
    asm("cvt.rna.tf32.f32 %0, %1;" : "=r"(u) : "f"(f));
    return u;
}

__device__ __forceinline__ void mma_tf32(float* d, const uint32_t* a,
                                         uint32_t b0, uint32_t b1) {
    asm volatile(
        "mma.sync.aligned.m16n8k8.row.col.f32.tf32.tf32.f32 "
        "{%0,%1,%2,%3}, {%4,%5,%6,%7}, {%8,%9}, {%0,%1,%2,%3};\n"
        : "+f"(d[0]), "+f"(d[1]), "+f"(d[2]), "+f"(d[3])
        : "r"(a[0]), "r"(a[1]), "r"(a[2]), "r"(a[3]), "r"(b0), "r"(b1));
}

// ---------------------------------------------------------------------------
// Projection: out[m, n] = sum_d X[m, d] * W[n, d] + bias[n]   (unchanged)
// ---------------------------------------------------------------------------
__global__ __launch_bounds__(256) void proj_kernel(const float* __restrict__ X,
                                                   const float* __restrict__ W,
                                                   const float* __restrict__ bias,
                                                   int which)
{
    __shared__ float Xs[64][32];
    __shared__ float Ws[64][33];

    float* out = (which == 0) ? g_qh : (which == 1) ? g_kh : g_vh;

    const int m0 = blockIdx.x * 64;
    const int t  = threadIdx.x;
    const int ty = t >> 4;
    const int tx = t & 15;

    float acc[4][4] = {};

    for (int k0 = 0; k0 < DM; k0 += 32) {
        #pragma unroll
        for (int j = 0; j < 2; j++) {
            int f   = t + j * 256;
            int row = f >> 3;
            int c4  = (f & 7) << 2;
            *(float4*)&Xs[row][c4] =
                *(const float4*)&X[(size_t)(m0 + row) * DM + k0 + c4];
        }
        #pragma unroll
        for (int j = 0; j < 8; j++) {
            int f  = t + j * 256;
            int n  = f >> 5;
            int kk = f & 31;
            Ws[n][kk] = W[(size_t)n * DM + k0 + kk];
        }
        __syncthreads();

        #pragma unroll
        for (int kk = 0; kk < 32; kk++) {
            float a[4], bv[4];
            #pragma unroll
            for (int r = 0; r < 4; r++) a[r] = Xs[ty * 4 + r][kk];
            #pragma unroll
            for (int c = 0; c < 4; c++) bv[c] = Ws[tx * 4 + c][kk];
            #pragma unroll
            for (int r = 0; r < 4; r++)
                #pragma unroll
                for (int c = 0; c < 4; c++)
                    acc[r][c] += a[r] * bv[c];
        }
        __syncthreads();
    }

    #pragma unroll
    for (int r = 0; r < 4; r++) {
        int m = m0 + ty * 4 + r;
        #pragma unroll
        for (int c = 0; c < 4; c++) {
            int n = tx * 4 + c;
            out[(size_t)m * DK + n] = acc[r][c] + bias[n];
        }
    }
}

// ---------------------------------------------------------------------------
// Flash attention with tf32 mma.sync (m16n8k8).
// Block: 128 queries, 8 warps (16 rows/warp), key tiles of 64.
// Q resident in A-fragments. K tile [key][dim] stride 80 (float4 B-frag loads,
// conflict-free). V tile [key][dv] stride 84 (scalar B-frag loads,
// conflict-free). P C-frags reused directly as A-frags (register permutation
// (c0,c2,c1,c3) + matching key-slot permutation on V loads).
// ---------------------------------------------------------------------------
#define KSTR 80
#define VSTR 84

__global__ __launch_bounds__(256) void attn_mma_kernel(const int* __restrict__ mask)
{
    __shared__ float sbuf[64 * KSTR + 64 * VSTR];   // 41984 B
    float* Ks = sbuf;                // [64][KSTR]
    float* Vs = sbuf + 64 * KSTR;    // [64][VSTR]
    float* Qs = sbuf;                // staging overlay [128][68] (8704 floats)

    const int b    = blockIdx.y;
    const int q0   = blockIdx.x * 128;
    const int t    = threadIdx.x;
    const int w    = t >> 5;
    const int lane = t & 31;
    const int gi   = lane >> 2;   // 0..7  (row-in-frag / n-in-frag)
    const int gc   = lane & 3;    // 0..3  (k-slot group)
    const float scale = 0.125f;   // 1/sqrt(64)

    // ---- stage Q through smem, extract resident A-fragments ----
    const float* qh = g_qh + ((size_t)b * SS + q0) * DK;
    #pragma unroll
    for (int j = 0; j < 8; j++) {
        int f   = t + j * 256;       // 0..2047
        int row = f >> 4;
        int c4  = (f & 15) << 2;
        *(float4*)&Qs[row * 68 + c4] = *(const float4*)&qh[row * DK + c4];
    }
    __syncthreads();

    uint32_t aq[8][4];
    {
        int ra = 16 * w + gi, rb = ra + 8;
        #pragma unroll
        for (int kc = 0; kc < 4; kc++) {
            int d = 16 * kc + 4 * gc;
            aq[2*kc  ][0] = f2tf(Qs[ra * 68 + d    ]);
            aq[2*kc  ][1] = f2tf(Qs[rb * 68 + d    ]);
            aq[2*kc  ][2] = f2tf(Qs[ra * 68 + d + 1]);
            aq[2*kc  ][3] = f2tf(Qs[rb * 68 + d + 1]);
            aq[2*kc+1][0] = f2tf(Qs[ra * 68 + d + 2]);
            aq[2*kc+1][1] = f2tf(Qs[rb * 68 + d + 2]);
            aq[2*kc+1][2] = f2tf(Qs[ra * 68 + d + 3]);
            aq[2*kc+1][3] = f2tf(Qs[rb * 68 + d + 3]);
        }
    }
    __syncthreads();   // Qs region about to be overwritten by Ks

    float oacc[8][4] = {};
    float m_a = -1e30f, m_b = -1e30f, l_a = 0.0f, l_b = 0.0f;

    const int qa = q0 + 16 * w + gi;     // row within batch (0..4095)
    const int qb = qa + 8;

    const float* khb = g_kh + (size_t)b * SS * DK;
    const float* vhb = g_vh + (size_t)b * SS * DK;
    const int2* mrow_a = (const int2*)(mask + (size_t)qa * SS);
    const int2* mrow_b = (const int2*)(mask + (size_t)qb * SS);

    for (int kt = 0; kt < SS; kt += 64) {
        // ---- stage K, V tiles (cvt to tf32 at store) ----
        #pragma unroll
        for (int j = 0; j < 4; j++) {
            int f   = t + j * 256;      // 0..1023
            int key = f >> 4;
            int c4  = (f & 15) << 2;
            float4 kv = *(const float4*)&khb[(size_t)(kt + key) * DK + c4];
            uint4  ku = { f2tf(kv.x), f2tf(kv.y), f2tf(kv.z), f2tf(kv.w) };
            *reinterpret_cast<uint4*>(Ks + key * KSTR + c4) = ku;
            float4 vv = *(const float4*)&vhb[(size_t)(kt + key) * DK + c4];
            uint4  vu = { f2tf(vv.x), f2tf(vv.y), f2tf(vv.z), f2tf(vv.w) };
            *reinterpret_cast<uint4*>(Vs + key * VSTR + c4) = vu;
        }
        __syncthreads();

        // ---- GEMM1: S = Q . K^T   (16 rows x 64 keys per warp) ----
        float sacc[8][4];
        #pragma unroll
        for (int nt = 0; nt < 8; nt++) {
            sacc[nt][0] = 0.f; sacc[nt][1] = 0.f;
            sacc[nt][2] = 0.f; sacc[nt][3] = 0.f;
        }
        #pragma unroll
        for (int nt = 0; nt < 8; nt++) {
            const float* kp = Ks + (8 * nt + gi) * KSTR + 4 * gc;
            #pragma unroll
            for (int kc = 0; kc < 4; kc++) {
                uint4 bb = *reinterpret_cast<const uint4*>(kp + 16 * kc);
                mma_tf32(sacc[nt], aq[2*kc    ], bb.x, bb.y);
                mma_tf32(sacc[nt], aq[2*kc + 1], bb.z, bb.w);
            }
        }

        // ---- scale + mask ----
        const int mbase = (kt >> 1) + gc;
        #pragma unroll
        for (int nt = 0; nt < 8; nt++) {
            int2 ma = mrow_a[mbase + 4 * nt];
            int2 mb = mrow_b[mbase + 4 * nt];
            sacc[nt][0] = ma.x ? sacc[nt][0] * scale : -1e9f;
            sacc[nt][1] = ma.y ? sacc[nt][1] * scale : -1e9f;
            sacc[nt][2] = mb.x ? sacc[nt][2] * scale : -1e9f;
            sacc[nt][3] = mb.y ? sacc[nt][3] * scale : -1e9f;
        }

        // ---- online softmax (rows a and b per thread group) ----
        float mxa = -1e30f, mxb = -1e30f;
        #pragma unroll
        for (int nt = 0; nt < 8; nt++) {
            mxa = fmaxf(mxa, fmaxf(sacc[nt][0], sacc[nt][1]));
            mxb = fmaxf(mxb, fmaxf(sacc[nt][2], sacc[nt][3]));
        }
        mxa = fmaxf(mxa, __shfl_xor_sync(0xffffffffu, mxa, 1));
        mxa = fmaxf(mxa, __shfl_xor_sync(0xffffffffu, mxa, 2));
        mxb = fmaxf(mxb, __shfl_xor_sync(0xffffffffu, mxb, 1));
        mxb = fmaxf(mxb, __shfl_xor_sync(0xffffffffu, mxb, 2));

        float mna = fmaxf(m_a, mxa);
        float mnb = fmaxf(m_b, mxb);
        float ca = __expf(m_a - mna);  m_a = mna;
        float cb = __expf(m_b - mnb);  m_b = mnb;

        uint32_t pf[8][4];
        float sla = 0.0f, slb = 0.0f;
        #pragma unroll
        for (int nt = 0; nt < 8; nt++) {
            float p0 = __expf(sacc[nt][0] - m_a);
            float p1 = __expf(sacc[nt][1] - m_a);
            float p2 = __expf(sacc[nt][2] - m_b);
            float p3 = __expf(sacc[nt][3] - m_b);
            sla += p0 + p1;
            slb += p2 + p3;
            // A-fragment ordering for GEMM2: (c0, c2, c1, c3)
            pf[nt][0] = f2tf(p0);
            pf[nt][1] = f2tf(p2);
            pf[nt][2] = f2tf(p1);
            pf[nt][3] = f2tf(p3);
        }
        sla += __shfl_xor_sync(0xffffffffu, sla, 1);
        sla += __shfl_xor_sync(0xffffffffu, sla, 2);
        slb += __shfl_xor_sync(0xffffffffu, slb, 1);
        slb += __shfl_xor_sync(0xffffffffu, slb, 2);
        l_a = l_a * ca + sla;
        l_b = l_b * cb + slb;

        #pragma unroll
        for (int nt = 0; nt < 8; nt++) {
            oacc[nt][0] *= ca; oacc[nt][1] *= ca;
            oacc[nt][2] *= cb; oacc[nt][3] *= cb;
        }

        // ---- GEMM2: O += P . V ----
        #pragma unroll
        for (int nt = 0; nt < 8; nt++) {
            const float* vp = Vs + 8 * nt + gi;     // dv column base
            #pragma unroll
            for (int g = 0; g < 8; g++) {
                uint32_t b0 = *reinterpret_cast<const uint32_t*>(
                                  vp + (8 * g + 2 * gc)     * VSTR);
                uint32_t b1 = *reinterpret_cast<const uint32_t*>(
                                  vp + (8 * g + 2 * gc + 1) * VSTR);
                mma_tf32(oacc[nt], pf[g], b0, b1);
            }
        }
        __syncthreads();   // tiles consumed; safe to overwrite next iteration
    }

    // ---- normalize + write ----
    float ia = 1.0f / l_a, ib = 1.0f / l_b;
    float* op = g_att + (size_t)b * SS * DK;
    #pragma unroll
    for (int nt = 0; nt < 8; nt++) {
        float2 oa = { oacc[nt][0] * ia, oacc[nt][1] * ia };
        *(float2*)&op[(size_t)qa * DK + 8 * nt + 2 * gc] = oa;
        float2 ob = { oacc[nt][2] * ib, oacc[nt][3] * ib };
        *(float2*)&op[(size_t)qb * DK + 8 * nt + 2 * gc] = ob;
    }
}

// ---------------------------------------------------------------------------
// Output projection: out[m, n] = sum_v att[m, v] * Wo[n, v] + bo[n] (unchanged)
// ---------------------------------------------------------------------------
__global__ __launch_bounds__(256) void outproj_kernel(const float* __restrict__ Wo,
                                                      const float* __restrict__ bo,
                                                      float* __restrict__ out)
{
    __shared__ float As[64][64];
    __shared__ float Ws[64][65];

    const int m0 = blockIdx.x * 64;
    const int n0 = blockIdx.y * 64;
    const int t  = threadIdx.x;
    const int ty = t >> 4;
    const int tx = t & 15;

    #pragma unroll
    for (int j = 0; j < 4; j++) {
        int f   = t + j * 256;
        int row = f >> 4;
        int c4  = (f & 15) << 2;
        *(float4*)&As[row][c4] =
            *(const float4*)&g_att[(size_t)(m0 + row) * DK + c4];
    }
    #pragma unroll
    for (int j = 0; j < 16; j++) {
        int f = t + j * 256;
        int n = f >> 6;
        int v = f & 63;
        Ws[n][v] = Wo[(size_t)(n0 + n) * DK + v];
    }
    __syncthreads();

    float acc[4][4] = {};
    #pragma unroll
    for (int kk = 0; kk < 64; kk++) {
        float a[4], bv[4];
        #pragma unroll
        for (int r = 0; r < 4; r++) a[r] = As[ty * 4 + r][kk];
        #pragma unroll
        for (int c = 0; c < 4; c++) bv[c] = Ws[tx * 4 + c][kk];
        #pragma unroll
        for (int r = 0; r < 4; r++)
            #pragma unroll
            for (int c = 0; c < 4; c++)
                acc[r][c] += a[r] * bv[c];
    }

    #pragma unroll
    for (int r = 0; r < 4; r++) {
        int m = m0 + ty * 4 + r;
        int n = n0 + tx * 4;
        float4 o;
        o.x = acc[r][0] + bo[n + 0];
        o.y = acc[r][1] + bo[n + 1];
        o.z = acc[r][2] + bo[n + 2];
        o.w = acc[r][3] + bo[n + 3];
        *(float4*)&out[(size_t)m * DM + n] = o;
    }
}

// ---------------------------------------------------------------------------
extern "C" void kernel_launch(void* const* d_in, const int* in_sizes, int n_in,
                              void* d_out, int out_size)
{
    const float* q    = (const float*)d_in[0];
    const float* k    = (const float*)d_in[1];
    const float* v    = (const float*)d_in[2];
    const int*   mask = (const int*)  d_in[3];
    const float* Wq   = (const float*)d_in[4];
    const float* bq   = (const float*)d_in[5];
    const float* Wk   = (const float*)d_in[6];
    const float* bk   = (const float*)d_in[7];
    const float* Wv   = (const float*)d_in[8];
    const float* bv   = (const float*)d_in[9];
    const float* Wo   = (const float*)d_in[10];
    const float* bo   = (const float*)d_in[11];
    float* out = (float*)d_out;

    const int M = BB * SS;  // 16384

    proj_kernel<<<M / 64, 256>>>(q, Wq, bq, 0);
    proj_kernel<<<M / 64, 256>>>(k, Wk, bk, 1);
    proj_kernel<<<M / 64, 256>>>(v, Wv, bv, 2);

    attn_mma_kernel<<<dim3(SS / 128, BB), 256>>>(mask);

    outproj_kernel<<<dim3(M / 64, DM / 64), 256>>>(Wo, bo, out);
}

// round 4
// speedup vs baseline: 2.0150x; 1.3384x over previous
#include <cuda_runtime.h>
#include <cstdint>

#define BB 4
#define SS 4096
#define DM 1024
#define DK 64

// Scratch (device globals per allocation-guard rules): 4 MB each
__device__ float g_qh[BB * SS * DK];
__device__ float g_kh[BB * SS * DK];
__device__ float g_vh[BB * SS * DK];
__device__ float g_att[BB * SS * DK];

// ---------------------------------------------------------------------------
// tf32 helpers
// ---------------------------------------------------------------------------
__device__ __forceinline__ uint32_t f2tf(float f) {
    uint32_t u;
    asm("cvt.rna.tf32.f32 %0, %1;" : "=r"(u) : "f"(f));
    return u;
}

__device__ __forceinline__ void mma_tf32(float* d, const uint32_t* a,
                                         uint32_t b0, uint32_t b1) {
    asm volatile(
        "mma.sync.aligned.m16n8k8.row.col.f32.tf32.tf32.f32 "
        "{%0,%1,%2,%3}, {%4,%5,%6,%7}, {%8,%9}, {%0,%1,%2,%3};\n"
        : "+f"(d[0]), "+f"(d[1]), "+f"(d[2]), "+f"(d[3])
        : "r"(a[0]), "r"(a[1]), "r"(a[2]), "r"(a[3]), "r"(b0), "r"(b1));
}

// ---------------------------------------------------------------------------
// QKV projection via tf32 mma: out[m,n] = sum_d X[m,d] * W[n,d] + bias[n]
// M = 16384, N = 64, K = 1024.  Block: 64 rows, 128 threads (4 warps),
// each warp computes 16 rows x 64 cols.  K-chunks of 64, layouts identical
// to the validated attention GEMM1 (Xs stride 68, Ws stride 80).
// ---------------------------------------------------------------------------
__global__ __launch_bounds__(128) void proj_mma_kernel(const float* __restrict__ X,
                                                       const float* __restrict__ W,
                                                       const float* __restrict__ bias,
                                                       int which)
{
    __shared__ uint32_t Xs[64 * 68];
    __shared__ uint32_t Ws[64 * 80];

    float* out = (which == 0) ? g_qh : (which == 1) ? g_kh : g_vh;

    const int m0   = blockIdx.x * 64;
    const int t    = threadIdx.x;
    const int w    = t >> 5;
    const int lane = t & 31;
    const int gi   = lane >> 2;
    const int gc   = lane & 3;

    float acc[8][4] = {};
    const int ra = 16 * w + gi, rb = ra + 8;

    for (int k0 = 0; k0 < DM; k0 += 64) {
        // stage X tile (64x64) and W tile (64x64), cvt to tf32 at store
        #pragma unroll
        for (int j = 0; j < 8; j++) {
            int f   = t + j * 128;        // 0..1023
            int row = f >> 4;
            int c4  = (f & 15) << 2;
            float4 xv = *(const float4*)&X[(size_t)(m0 + row) * DM + k0 + c4];
            uint4  xu = { f2tf(xv.x), f2tf(xv.y), f2tf(xv.z), f2tf(xv.w) };
            *reinterpret_cast<uint4*>(&Xs[row * 68 + c4]) = xu;
            float4 wv = *(const float4*)&W[(size_t)row * DM + k0 + c4];
            uint4  wu = { f2tf(wv.x), f2tf(wv.y), f2tf(wv.z), f2tf(wv.w) };
            *reinterpret_cast<uint4*>(&Ws[row * 80 + c4]) = wu;
        }
        __syncthreads();

        // A fragments for this k-chunk
        uint32_t aq[8][4];
        #pragma unroll
        for (int kc = 0; kc < 4; kc++) {
            int d = 16 * kc + 4 * gc;
            aq[2*kc  ][0] = Xs[ra * 68 + d    ];
            aq[2*kc  ][1] = Xs[rb * 68 + d    ];
            aq[2*kc  ][2] = Xs[ra * 68 + d + 1];
            aq[2*kc  ][3] = Xs[rb * 68 + d + 1];
            aq[2*kc+1][0] = Xs[ra * 68 + d + 2];
            aq[2*kc+1][1] = Xs[rb * 68 + d + 2];
            aq[2*kc+1][2] = Xs[ra * 68 + d + 3];
            aq[2*kc+1][3] = Xs[rb * 68 + d + 3];
        }

        #pragma unroll
        for (int nt = 0; nt < 8; nt++) {
            const uint32_t* kp = Ws + (8 * nt + gi) * 80 + 4 * gc;
            #pragma unroll
            for (int kc = 0; kc < 4; kc++) {
                uint4 bb = *reinterpret_cast<const uint4*>(kp + 16 * kc);
                mma_tf32(acc[nt], aq[2*kc    ], bb.x, bb.y);
                mma_tf32(acc[nt], aq[2*kc + 1], bb.z, bb.w);
            }
        }
        __syncthreads();
    }

    #pragma unroll
    for (int nt = 0; nt < 8; nt++) {
        int n = 8 * nt + 2 * gc;
        float2 b2 = *(const float2*)&bias[n];
        float2 oa = { acc[nt][0] + b2.x, acc[nt][1] + b2.y };
        *(float2*)&out[(size_t)(m0 + ra) * DK + n] = oa;
        float2 ob = { acc[nt][2] + b2.x, acc[nt][3] + b2.y };
        *(float2*)&out[(size_t)(m0 + rb) * DK + n] = ob;
    }
}

// ---------------------------------------------------------------------------
// Output projection via tf32 mma: out[m,n] = sum_v att[m,v]*Wo[n,v] + bo[n]
// M = 16384, N = 1024, K = 64.  Block: 64 rows x 64 cols, 128 threads.
// ---------------------------------------------------------------------------
__global__ __launch_bounds__(128) void outproj_mma_kernel(const float* __restrict__ Wo,
                                                          const float* __restrict__ bo,
                                                          float* __restrict__ out)
{
    __shared__ uint32_t As[64 * 68];
    __shared__ uint32_t Ws[64 * 80];

    const int m0   = blockIdx.x * 64;
    const int n0   = blockIdx.y * 64;
    const int t    = threadIdx.x;
    const int w    = t >> 5;
    const int lane = t & 31;
    const int gi   = lane >> 2;
    const int gc   = lane & 3;

    #pragma unroll
    for (int j = 0; j < 8; j++) {
        int f   = t + j * 128;
        int row = f >> 4;
        int c4  = (f & 15) << 2;
        float4 av = *(const float4*)&g_att[(size_t)(m0 + row) * DK + c4];
        uint4  au = { f2tf(av.x), f2tf(av.y), f2tf(av.z), f2tf(av.w) };
        *reinterpret_cast<uint4*>(&As[row * 68 + c4]) = au;
        float4 wv = *(const float4*)&Wo[(size_t)(n0 + row) * DK + c4];
        uint4  wu = { f2tf(wv.x), f2tf(wv.y), f2tf(wv.z), f2tf(wv.w) };
        *reinterpret_cast<uint4*>(&Ws[row * 80 + c4]) = wu;
    }
    __syncthreads();

    const int ra = 16 * w + gi, rb = ra + 8;

    uint32_t aq[8][4];
    #pragma unroll
    for (int kc = 0; kc < 4; kc++) {
        int d = 16 * kc + 4 * gc;
        aq[2*kc  ][0] = As[ra * 68 + d    ];
        aq[2*kc  ][1] = As[rb * 68 + d    ];
        aq[2*kc  ][2] = As[ra * 68 + d + 1];
        aq[2*kc  ][3] = As[rb * 68 + d + 1];
        aq[2*kc+1][0] = As[ra * 68 + d + 2];
        aq[2*kc+1][1] = As[rb * 68 + d + 2];
        aq[2*kc+1][2] = As[ra * 68 + d + 3];
        aq[2*kc+1][3] = As[rb * 68 + d + 3];
    }

    float acc[8][4] = {};
    #pragma unroll
    for (int nt = 0; nt < 8; nt++) {
        const uint32_t* kp = Ws + (8 * nt + gi) * 80 + 4 * gc;
        #pragma unroll
        for (int kc = 0; kc < 4; kc++) {
            uint4 bb = *reinterpret_cast<const uint4*>(kp + 16 * kc);
            mma_tf32(acc[nt], aq[2*kc    ], bb.x, bb.y);
            mma_tf32(acc[nt], aq[2*kc + 1], bb.z, bb.w);
        }
    }

    #pragma unroll
    for (int nt = 0; nt < 8; nt++) {
        int n = n0 + 8 * nt + 2 * gc;
        float2 b2 = *(const float2*)&bo[n];
        float2 oa = { acc[nt][0] + b2.x, acc[nt][1] + b2.y };
        *(float2*)&out[(size_t)(m0 + ra) * DM + n] = oa;
        float2 ob = { acc[nt][2] + b2.x, acc[nt][3] + b2.y };
        *(float2*)&out[(size_t)(m0 + rb) * DM + n] = ob;
    }
}

// ---------------------------------------------------------------------------
// Flash attention with tf32 mma.sync (m16n8k8).
// Block: 64 queries, 4 warps (16 rows/warp), key tiles of 64.
// 128-thread blocks -> 3 blocks/SM by regs (was 1 at 256 thr), grid 256.
// ---------------------------------------------------------------------------
#define KSTR 80
#define VSTR 84

__global__ __launch_bounds__(128) void attn_mma_kernel(const int* __restrict__ mask)
{
    __shared__ float sbuf[64 * KSTR + 64 * VSTR];   // 41984 B
    float* Ks = sbuf;                // [64][KSTR]
    float* Vs = sbuf + 64 * KSTR;    // [64][VSTR]
    float* Qs = sbuf;                // staging overlay [64][68]

    const int b    = blockIdx.y;
    const int q0   = blockIdx.x * 64;
    const int t    = threadIdx.x;
    const int w    = t >> 5;          // 0..3
    const int lane = t & 31;
    const int gi   = lane >> 2;
    const int gc   = lane & 3;
    const float scale = 0.125f;       // 1/sqrt(64)

    // ---- stage Q through smem, extract resident A-fragments ----
    const float* qh = g_qh + ((size_t)b * SS + q0) * DK;
    #pragma unroll
    for (int j = 0; j < 8; j++) {
        int f   = t + j * 128;        // 0..1023
        int row = f >> 4;
        int c4  = (f & 15) << 2;
        *(float4*)&Qs[row * 68 + c4] = *(const float4*)&qh[row * DK + c4];
    }
    __syncthreads();

    uint32_t aq[8][4];
    {
        int ra = 16 * w + gi, rb = ra + 8;
        #pragma unroll
        for (int kc = 0; kc < 4; kc++) {
            int d = 16 * kc + 4 * gc;
            aq[2*kc  ][0] = f2tf(Qs[ra * 68 + d    ]);
            aq[2*kc  ][1] = f2tf(Qs[rb * 68 + d    ]);
            aq[2*kc  ][2] = f2tf(Qs[ra * 68 + d + 1]);
            aq[2*kc  ][3] = f2tf(Qs[rb * 68 + d + 1]);
            aq[2*kc+1][0] = f2tf(Qs[ra * 68 + d + 2]);
            aq[2*kc+1][1] = f2tf(Qs[rb * 68 + d + 2]);
            aq[2*kc+1][2] = f2tf(Qs[ra * 68 + d + 3]);
            aq[2*kc+1][3] = f2tf(Qs[rb * 68 + d + 3]);
        }
    }
    __syncthreads();   // Qs region about to be overwritten by Ks

    float oacc[8][4] = {};
    float m_a = -1e30f, m_b = -1e30f, l_a = 0.0f, l_b = 0.0f;

    const int qa = q0 + 16 * w + gi;     // row within batch (0..4095)
    const int qb = qa + 8;

    const float* khb = g_kh + (size_t)b * SS * DK;
    const float* vhb = g_vh + (size_t)b * SS * DK;
    const int2* mrow_a = (const int2*)(mask + (size_t)qa * SS);
    const int2* mrow_b = (const int2*)(mask + (size_t)qb * SS);

    for (int kt = 0; kt < SS; kt += 64) {
        // ---- stage K, V tiles (cvt to tf32 at store) ----
        #pragma unroll
        for (int j = 0; j < 8; j++) {
            int f   = t + j * 128;      // 0..1023
            int key = f >> 4;
            int c4  = (f & 15) << 2;
            float4 kv = *(const float4*)&khb[(size_t)(kt + key) * DK + c4];
            uint4  ku = { f2tf(kv.x), f2tf(kv.y), f2tf(kv.z), f2tf(kv.w) };
            *reinterpret_cast<uint4*>(Ks + key * KSTR + c4) = ku;
            float4 vv = *(const float4*)&vhb[(size_t)(kt + key) * DK + c4];
            uint4  vu = { f2tf(vv.x), f2tf(vv.y), f2tf(vv.z), f2tf(vv.w) };
            *reinterpret_cast<uint4*>(Vs + key * VSTR + c4) = vu;
        }
        __syncthreads();

        // ---- GEMM1: S = Q . K^T   (16 rows x 64 keys per warp) ----
        float sacc[8][4];
        #pragma unroll
        for (int nt = 0; nt < 8; nt++) {
            sacc[nt][0] = 0.f; sacc[nt][1] = 0.f;
            sacc[nt][2] = 0.f; sacc[nt][3] = 0.f;
        }
        #pragma unroll
        for (int nt = 0; nt < 8; nt++) {
            const float* kp = Ks + (8 * nt + gi) * KSTR + 4 * gc;
            #pragma unroll
            for (int kc = 0; kc < 4; kc++) {
                uint4 bb = *reinterpret_cast<const uint4*>(kp + 16 * kc);
                mma_tf32(sacc[nt], aq[2*kc    ], bb.x, bb.y);
                mma_tf32(sacc[nt], aq[2*kc + 1], bb.z, bb.w);
            }
        }

        // ---- scale + mask ----
        const int mbase = (kt >> 1) + gc;
        #pragma unroll
        for (int nt = 0; nt < 8; nt++) {
            int2 ma = mrow_a[mbase + 4 * nt];
            int2 mb = mrow_b[mbase + 4 * nt];
            sacc[nt][0] = ma.x ? sacc[nt][0] * scale : -1e9f;
            sacc[nt][1] = ma.y ? sacc[nt][1] * scale : -1e9f;
            sacc[nt][2] = mb.x ? sacc[nt][2] * scale : -1e9f;
            sacc[nt][3] = mb.y ? sacc[nt][3] * scale : -1e9f;
        }

        // ---- online softmax ----
        float mxa = -1e30f, mxb = -1e30f;
        #pragma unroll
        for (int nt = 0; nt < 8; nt++) {
            mxa = fmaxf(mxa, fmaxf(sacc[nt][0], sacc[nt][1]));
            mxb = fmaxf(mxb, fmaxf(sacc[nt][2], sacc[nt][3]));
        }
        mxa = fmaxf(mxa, __shfl_xor_sync(0xffffffffu, mxa, 1));
        mxa = fmaxf(mxa, __shfl_xor_sync(0xffffffffu, mxa, 2));
        mxb = fmaxf(mxb, __shfl_xor_sync(0xffffffffu, mxb, 1));
        mxb = fmaxf(mxb, __shfl_xor_sync(0xffffffffu, mxb, 2));

        float mna = fmaxf(m_a, mxa);
        float mnb = fmaxf(m_b, mxb);
        float ca = __expf(m_a - mna);  m_a = mna;
        float cb = __expf(m_b - mnb);  m_b = mnb;

        uint32_t pf[8][4];
        float sla = 0.0f, slb = 0.0f;
        #pragma unroll
        for (int nt = 0; nt < 8; nt++) {
            float p0 = __expf(sacc[nt][0] - m_a);
            float p1 = __expf(sacc[nt][1] - m_a);
            float p2 = __expf(sacc[nt][2] - m_b);
            float p3 = __expf(sacc[nt][3] - m_b);
            sla += p0 + p1;
            slb += p2 + p3;
            // A-fragment ordering for GEMM2: (c0, c2, c1, c3)
            pf[nt][0] = f2tf(p0);
            pf[nt][1] = f2tf(p2);
            pf[nt][2] = f2tf(p1);
            pf[nt][3] = f2tf(p3);
        }
        sla += __shfl_xor_sync(0xffffffffu, sla, 1);
        sla += __shfl_xor_sync(0xffffffffu, sla, 2);
        slb += __shfl_xor_sync(0xffffffffu, slb, 1);
        slb += __shfl_xor_sync(0xffffffffu, slb, 2);
        l_a = l_a * ca + sla;
        l_b = l_b * cb + slb;

        #pragma unroll
        for (int nt = 0; nt < 8; nt++) {
            oacc[nt][0] *= ca; oacc[nt][1] *= ca;
            oacc[nt][2] *= cb; oacc[nt][3] *= cb;
        }

        // ---- GEMM2: O += P . V ----
        #pragma unroll
        for (int nt = 0; nt < 8; nt++) {
            const float* vp = Vs + 8 * nt + gi;     // dv column base
            #pragma unroll
            for (int g = 0; g < 8; g++) {
                uint32_t b0 = *reinterpret_cast<const uint32_t*>(
                                  vp + (8 * g + 2 * gc)     * VSTR);
                uint32_t b1 = *reinterpret_cast<const uint32_t*>(
                                  vp + (8 * g + 2 * gc + 1) * VSTR);
                mma_tf32(oacc[nt], pf[g], b0, b1);
            }
        }
        __syncthreads();   // tiles consumed; safe to overwrite next iteration
    }

    // ---- normalize + write ----
    float ia = 1.0f / l_a, ib = 1.0f / l_b;
    float* op = g_att + (size_t)b * SS * DK;
    #pragma unroll
    for (int nt = 0; nt < 8; nt++) {
        float2 oa = { oacc[nt][0] * ia, oacc[nt][1] * ia };
        *(float2*)&op[(size_t)qa * DK + 8 * nt + 2 * gc] = oa;
        float2 ob = { oacc[nt][2] * ib, oacc[nt][3] * ib };
        *(float2*)&op[(size_t)qb * DK + 8 * nt + 2 * gc] = ob;
    }
}

// ---------------------------------------------------------------------------
extern "C" void kernel_launch(void* const* d_in, const int* in_sizes, int n_in,
                              void* d_out, int out_size)
{
    const float* q    = (const float*)d_in[0];
    const float* k    = (const float*)d_in[1];
    const float* v    = (const float*)d_in[2];
    const int*   mask = (const int*)  d_in[3];
    const float* Wq   = (const float*)d_in[4];
    const float* bq   = (const float*)d_in[5];
    const float* Wk   = (const float*)d_in[6];
    const float* bk   = (const float*)d_in[7];
    const float* Wv   = (const float*)d_in[8];
    const float* bv   = (const float*)d_in[9];
    const float* Wo   = (const float*)d_in[10];
    const float* bo   = (const float*)d_in[11];
    float* out = (float*)d_out;

    const int M = BB * SS;  // 16384

    proj_mma_kernel<<<M / 64, 128>>>(q, Wq, bq, 0);
    proj_mma_kernel<<<M / 64, 128>>>(k, Wk, bk, 1);
    proj_mma_kernel<<<M / 64, 128>>>(v, Wv, bv, 2);

    attn_mma_kernel<<<dim3(SS / 64, BB), 128>>>(mask);

    outproj_mma_kernel<<<dim3(M / 64, DM / 64), 128>>>(Wo, bo, out);
}